// round 13
// baseline (speedup 1.0000x reference)
#include <cuda_runtime.h>
#include <cuda_bf16.h>
#include <cstdint>

// Problem constants (fixed by setup_inputs)
#define NB 4
#define CC 128
#define HH 160
#define WW 320
#define DD 48
#define CHAN_STRIDE (HH * WW)

#define NTHR 256        // 8 warps, each owns 16 w-rows + its 64-wide g band
#define MT   128        // w rows per CTA tile
#define CHS  16         // channels per pipeline chunk
#define NC   (CC / CHS) // 8 chunks

// ---- smem byte layout (dynamic): bf16 tiles only, double-buffered ----
#define LH_B   (CHS * 136 * 2)           // 4352  (bf16 [16][136], 272B rows)
#define RH_B   (CHS * 184 * 2)           // 5888  (bf16 [16][184], 368B rows)
#define OFF_LH 0
#define OFF_LL (OFF_LH + 2 * LH_B)       // 8704
#define OFF_RH (OFF_LL + 2 * LH_B)       // 17408
#define OFF_RL (OFF_RH + 2 * RH_B)       // 29184
#define SMEM_TOTAL (OFF_RL + 2 * RH_B)   // 40960
// epilogue G[128][65] fp32 (33280 B) reuses the tile region (after final sync)
#define GSTR 65

__device__ __forceinline__ uint32_t smem_u32(const void* p) {
    return (uint32_t)__cvta_generic_to_shared(p);
}
// ldmatrix 4x 8x8 b16 tiles, transposed in HW
__device__ __forceinline__ void ldsm4t(uint32_t* r, uint32_t addr) {
    asm volatile("ldmatrix.sync.aligned.m8n8.x4.trans.shared.b16 {%0,%1,%2,%3}, [%4];"
                 : "=r"(r[0]), "=r"(r[1]), "=r"(r[2]), "=r"(r[3]) : "r"(addr));
}
// D(16x8,f32) += A(16x16,bf16 row) * B(16x8,bf16 col)
__device__ __forceinline__ void mma16816(float* d, const uint32_t* a, const uint32_t* b) {
    asm volatile(
        "mma.sync.aligned.m16n8k16.row.col.f32.bf16.bf16.f32 "
        "{%0,%1,%2,%3}, {%4,%5,%6,%7}, {%8,%9}, {%0,%1,%2,%3};"
        : "+f"(d[0]), "+f"(d[1]), "+f"(d[2]), "+f"(d[3])
        : "r"(a[0]), "r"(a[1]), "r"(a[2]), "r"(a[3]), "r"(b[0]), "r"(b[1]));
}
// fp32 pair (w, w+1) -> hi/lo bf16x2 words (low 16 bits = first element)
__device__ __forceinline__ void split_pair(float a, float b, uint32_t& hi, uint32_t& lo) {
    __nv_bfloat162 h2 = __floats2bfloat162_rn(a, b);
    hi = *reinterpret_cast<uint32_t*>(&h2);
    float ra = a - __bfloat162float(h2.x);
    float rb = b - __bfloat162float(h2.y);
    __nv_bfloat162 l2 = __floats2bfloat162_rn(ra, rb);
    lo = *reinterpret_cast<uint32_t*>(&l2);
}
// store hi/lo words of two adjacent pairs as one STS.64 each
__device__ __forceinline__ void sts64(char* base, uint32_t off, uint32_t a, uint32_t b) {
    asm volatile("st.shared.v2.u32 [%0], {%1, %2};"
                 :: "r"(smem_u32(base) + off), "r"(a), "r"(b) : "memory");
}

__global__ void __launch_bounds__(NTHR, 2)
cost_volume_mma_kernel(const float* __restrict__ left,
                       const float* __restrict__ right,
                       float* __restrict__ out)
{
    extern __shared__ char sm[];
    const uint32_t smb = smem_u32(sm);
    const int tid  = threadIdx.x;
    const int lane = tid & 31;
    const int wid  = tid >> 5;            // 0..7
    const int i0   = wid * 16;            // warp's w-rows i0..i0+15; g-band [i0, i0+64)
    const int w0   = blockIdx.x * MT;     // 0,128,256 (last tile zero-padded)
    const int h    = blockIdx.y;
    const int n    = blockIdx.z;

    const float* lrow = left  + (size_t)n * CC * CHAN_STRIDE + (size_t)h * WW;
    const float* rrow = right + (size_t)n * CC * CHAN_STRIDE + (size_t)h * WW;

    // per-thread load slots: L 2 float4, R up to 3 float4
    // L: idx = tid + it*256 -> c = idx>>5, q = idx&31, gw = w0 + 4q
    // R: idx = tid + it*256 (<704) -> c = idx/44, q = idx%44, gw = w0 - 48 + 4q
    float4 Lr[2], Rr[3];

    auto load_regs = [&](int s) {
        const float* lb = lrow + (size_t)(s * CHS) * CHAN_STRIDE;
        const float* rb = rrow + (size_t)(s * CHS) * CHAN_STRIDE;
        #pragma unroll
        for (int it = 0; it < 2; it++) {
            int idx = tid + it * NTHR;
            int c = idx >> 5, q = idx & 31;
            int gw = w0 + 4 * q;
            Lr[it] = (gw < WW) ? *(const float4*)(lb + (size_t)c * CHAN_STRIDE + gw)
                               : make_float4(0.f, 0.f, 0.f, 0.f);
        }
        #pragma unroll
        for (int it = 0; it < 3; it++) {
            int idx = tid + it * NTHR;
            if (idx < CHS * 44) {
                int c = idx / 44, q = idx - c * 44;
                int gw = w0 - 48 + 4 * q;
                Rr[it] = (gw >= 0 && gw < WW)
                           ? *(const float4*)(rb + (size_t)c * CHAN_STRIDE + gw)
                           : make_float4(0.f, 0.f, 0.f, 0.f);
            }
        }
    };

    // convert register chunk -> bf16 hi/lo tiles (padded strides, conflict-free)
    auto convert = [&](int buf) {
        char* lh = sm + OFF_LH + buf * LH_B;
        char* ll = sm + OFF_LL + buf * LH_B;
        char* rh = sm + OFF_RH + buf * RH_B;
        char* rl = sm + OFF_RL + buf * RH_B;
        #pragma unroll
        for (int it = 0; it < 2; it++) {
            int idx = tid + it * NTHR;
            int c = idx >> 5, q = idx & 31;
            uint32_t h0, l0, h1, l1;
            split_pair(Lr[it].x, Lr[it].y, h0, l0);
            split_pair(Lr[it].z, Lr[it].w, h1, l1);
            uint32_t off = (uint32_t)(c * 272 + 8 * q);
            sts64(lh, off, h0, h1);
            sts64(ll, off, l0, l1);
        }
        #pragma unroll
        for (int it = 0; it < 3; it++) {
            int idx = tid + it * NTHR;
            if (idx < CHS * 44) {
                int c = idx / 44, q = idx - c * 44;
                uint32_t h0, l0, h1, l1;
                split_pair(Rr[it].x, Rr[it].y, h0, l0);
                split_pair(Rr[it].z, Rr[it].w, h1, l1);
                uint32_t off = (uint32_t)(c * 368 + 8 * q);
                sts64(rh, off, h0, h1);
                sts64(rl, off, l0, l1);
            }
        }
    };

    // per-lane ldmatrix address offsets (matrix m = lane>>3, row r = lane&7)
    const int mat = lane >> 3, r8 = lane & 7;
    // A tiles [k][i]: mats (i0,k0-7),(i0+8,k0-7),(i0,k8-15),(i0+8,k8-15)
    const uint32_t a_off = (uint32_t)((r8 + 8 * (mat >> 1)) * 272 + (i0 + 8 * (mat & 1)) * 2);
    // B tiles [k][g]: mats (k0-7,g),(k8-15,g),(k0-7,g+8),(k8-15,g+8); g base = i0
    const uint32_t b_off = (uint32_t)((r8 + 8 * (mat & 1)) * 368 + (i0 + 8 * (mat >> 1)) * 2);

    float acc[8][4];
    #pragma unroll
    for (int j = 0; j < 8; j++)
        #pragma unroll
        for (int q = 0; q < 4; q++) acc[j][q] = 0.0f;

    // ---- 24 HMMAs per warp per chunk: 3 split terms x 8 n-frags ----
    auto compute = [&](int buf) {
        uint32_t ah[4], al[4];
        ldsm4t(ah, smb + OFF_LH + buf * LH_B + a_off);
        ldsm4t(al, smb + OFF_LL + buf * LH_B + a_off);
        uint32_t rhb = smb + OFF_RH + buf * RH_B + b_off;
        uint32_t rlb = smb + OFF_RL + buf * RH_B + b_off;
        #pragma unroll
        for (int jb = 0; jb < 4; jb++) {           // 16 g-cols per jb (2 n-frags)
            uint32_t bh[4], bl[4];
            ldsm4t(bh, rhb + jb * 32);
            ldsm4t(bl, rlb + jb * 32);
            mma16816(acc[2 * jb],     ah, bh);
            mma16816(acc[2 * jb],     ah, bl);
            mma16816(acc[2 * jb],     al, bh);
            mma16816(acc[2 * jb + 1], ah, bh + 2);
            mma16816(acc[2 * jb + 1], ah, bl + 2);
            mma16816(acc[2 * jb + 1], al, bh + 2);
        }
    };

    // ================= main pipeline: ONE barrier per chunk =================
    // conv(s) -> [LDG s+1] -> sync -> compute(s); double-buffered tiles make
    // conv(s+1) (post-sync) safe against compute(s-1) (pre-sync), and conv(s+1)
    // overlaps compute(s) on the other buffer.
    load_regs(0);
    for (int s = 0; s < NC; s++) {
        int buf = s & 1;
        convert(buf);
        if (s + 1 < NC) load_regs(s + 1);   // DRAM latency hides behind sync+MMA
        __syncthreads();
        compute(buf);
    }

    // ---- epilogue: frags -> smem G[128][65] -> coalesced band stores ----
    __syncthreads();                        // all compute done before tiles reused as G
    float* Gs = (float*)sm;
    {
        int gid = lane >> 2, t4 = lane & 3;
        int ro = (i0 + gid) * GSTR, c0 = 2 * t4;
        #pragma unroll
        for (int j = 0; j < 8; j++) {
            Gs[ro + 8 * j + c0]                 = acc[j][0];
            Gs[ro + 8 * j + c0 + 1]             = acc[j][1];
            Gs[ro + 8 * GSTR + 8 * j + c0]      = acc[j][2];
            Gs[ro + 8 * GSTR + 8 * j + c0 + 1]  = acc[j][3];
        }
    }
    __syncthreads();
    {
        int i  = tid & 127;
        int dh = (tid >> 7) * 24;
        if (w0 + i < WW) {
            #pragma unroll
            for (int dj = 0; dj < 24; dj++) {
                int d = dh + dj;    // g - i0 = (i&15) + 48 - d
                out[(((size_t)(n * DD + d)) * HH + h) * WW + w0 + i] =
                    Gs[i * GSTR + (i & 15) + 48 - d];
            }
        }
    }
}

extern "C" void kernel_launch(void* const* d_in, const int* in_sizes, int n_in,
                              void* d_out, int out_size)
{
    const float* left  = (const float*)d_in[0];
    const float* right = (const float*)d_in[1];
    float* out = (float*)d_out;

    cudaFuncSetAttribute(cost_volume_mma_kernel,
                         cudaFuncAttributeMaxDynamicSharedMemorySize, SMEM_TOTAL);

    dim3 grid((WW + MT - 1) / MT, HH, NB);   // (3, 160, 4)
    cost_volume_mma_kernel<<<grid, NTHR, SMEM_TOTAL>>>(left, right, out);
}

// round 14
// speedup vs baseline: 1.2548x; 1.2548x over previous
#include <cuda_runtime.h>
#include <cuda_bf16.h>
#include <cstdint>

// Problem constants (fixed by setup_inputs)
#define NB 4
#define CC 128
#define HH 160
#define WW 320
#define DD 48
#define CHAN_STRIDE (HH * WW)

#define NTHR 256        // 8 warps, each owns 16 w-rows + its 64-wide g band
#define MT   128        // w rows per CTA tile
#define CHS  16         // channels per pipeline chunk
#define NC   (CC / CHS) // 8 chunks

// ---- smem byte layout (dynamic) ----
#define OFF_FL 0                         // fp32 L stage [2][16][128]
#define FL_B   (CHS * 128 * 4)           // 8192
#define OFF_FR (OFF_FL + 2 * FL_B)       // 16384; fp32 R stage [2][16][176]
#define FR_B   (CHS * 176 * 4)           // 11264
#define OFF_LH (OFF_FR + 2 * FR_B)       // 38912; bf16 Lh [2][16][136] (272B rows)
#define LH_B   (CHS * 136 * 2)           // 4352
#define OFF_LL (OFF_LH + 2 * LH_B)       // 47616
#define OFF_RH (OFF_LL + 2 * LH_B)       // 56320; bf16 Rh [2][16][184] (368B rows)
#define RH_B   (CHS * 184 * 2)           // 5888
#define OFF_RL (OFF_RH + 2 * RH_B)       // 68096
#define SMEM_TOTAL (OFF_RL + 2 * RH_B)   // 79872
// epilogue G[128][65] fp32 (33280 B) fits in the dead fp32 staging region
#define GSTR 65

__device__ __forceinline__ uint32_t smem_u32(const void* p) {
    return (uint32_t)__cvta_generic_to_shared(p);
}
// 16B async copy, global->shared, zero-fill when bytes==0 (halo padding).
__device__ __forceinline__ void cp16(uint32_t dst, const void* src, int bytes) {
    asm volatile("cp.async.cg.shared.global [%0], [%1], 16, %2;"
                 :: "r"(dst), "l"(src), "r"(bytes));
}
// ldmatrix 4x 8x8 b16 tiles, transposed in HW
__device__ __forceinline__ void ldsm4t(uint32_t* r, uint32_t addr) {
    asm volatile("ldmatrix.sync.aligned.m8n8.x4.trans.shared.b16 {%0,%1,%2,%3}, [%4];"
                 : "=r"(r[0]), "=r"(r[1]), "=r"(r[2]), "=r"(r[3]) : "r"(addr));
}
// D(16x8,f32) += A(16x16,bf16 row) * B(16x8,bf16 col)
__device__ __forceinline__ void mma16816(float* d, const uint32_t* a, const uint32_t* b) {
    asm volatile(
        "mma.sync.aligned.m16n8k16.row.col.f32.bf16.bf16.f32 "
        "{%0,%1,%2,%3}, {%4,%5,%6,%7}, {%8,%9}, {%0,%1,%2,%3};"
        : "+f"(d[0]), "+f"(d[1]), "+f"(d[2]), "+f"(d[3])
        : "r"(a[0]), "r"(a[1]), "r"(a[2]), "r"(a[3]), "r"(b[0]), "r"(b[1]));
}
// fp32 pair (w, w+1) -> hi/lo bf16x2 words (low 16 bits = first element)
__device__ __forceinline__ void split_pair(float a, float b, uint32_t& hi, uint32_t& lo) {
    __nv_bfloat162 h2 = __floats2bfloat162_rn(a, b);
    hi = *reinterpret_cast<uint32_t*>(&h2);
    float ra = a - __bfloat162float(h2.x);
    float rb = b - __bfloat162float(h2.y);
    __nv_bfloat162 l2 = __floats2bfloat162_rn(ra, rb);
    lo = *reinterpret_cast<uint32_t*>(&l2);
}
// store two 32-bit words as one STS.64
__device__ __forceinline__ void sts64(char* base, uint32_t off, uint32_t a, uint32_t b) {
    asm volatile("st.shared.v2.u32 [%0], {%1, %2};"
                 :: "r"(smem_u32(base) + off), "r"(a), "r"(b) : "memory");
}

__global__ void __launch_bounds__(NTHR, 2)
cost_volume_mma_kernel(const float* __restrict__ left,
                       const float* __restrict__ right,
                       float* __restrict__ out)
{
    extern __shared__ char sm[];
    const uint32_t smb = smem_u32(sm);
    const int tid  = threadIdx.x;
    const int lane = tid & 31;
    const int wid  = tid >> 5;            // 0..7
    const int i0   = wid * 16;            // warp's w-rows i0..i0+15; g-band [i0, i0+64)
    const int w0   = blockIdx.x * MT;     // 0,128,256 (last tile zero-padded)
    const int h    = blockIdx.y;
    const int n    = blockIdx.z;

    const float* lrow = left  + (size_t)n * CC * CHAN_STRIDE + (size_t)h * WW;
    const float* rrow = right + (size_t)n * CC * CHAN_STRIDE + (size_t)h * WW;

    // ---- cp.async stage of one 16-channel chunk (fp32) ----
    // thread->data mapping MUST match convert() below (self-owned data).
    auto cp_stage = [&](int s, int buf) {
        const float* lb = lrow + (size_t)(s * CHS) * CHAN_STRIDE;
        const float* rb = rrow + (size_t)(s * CHS) * CHAN_STRIDE;
        #pragma unroll
        for (int it = 0; it < 2; it++) {           // L: 512 float4
            int idx = tid + it * NTHR;
            int c = idx >> 5, q = idx & 31;
            int gw = w0 + 4 * q;
            bool ok = (gw < WW);
            cp16(smb + OFF_FL + buf * FL_B + c * 512 + 16 * q,
                 ok ? lb + (size_t)c * CHAN_STRIDE + gw : lb, ok ? 16 : 0);
        }
        #pragma unroll
        for (int it = 0; it < 3; it++) {           // R: 704 float4
            int idx = tid + it * NTHR;
            if (idx < CHS * 44) {
                int c = idx / 44, q = idx - c * 44;
                int gw = w0 - 48 + 4 * q;
                bool ok = (gw >= 0) && (gw < WW);
                cp16(smb + OFF_FR + buf * FR_B + c * 704 + 16 * q,
                     ok ? rb + (size_t)c * CHAN_STRIDE + gw : rb, ok ? 16 : 0);
            }
        }
        asm volatile("cp.async.commit_group;");
    };

    // ---- convert: each thread splits exactly the float4s it cp'd ----
    // (thread-local wait_group is then sufficient; NO barrier needed cp->conv)
    auto convert = [&](int buf) {
        const float* Lf = (const float*)(sm + OFF_FL + buf * FL_B);
        const float* Rf = (const float*)(sm + OFF_FR + buf * FR_B);
        char* lh = sm + OFF_LH + buf * LH_B;
        char* ll = sm + OFF_LL + buf * LH_B;
        char* rh = sm + OFF_RH + buf * RH_B;
        char* rl = sm + OFF_RL + buf * RH_B;
        #pragma unroll
        for (int it = 0; it < 2; it++) {
            int idx = tid + it * NTHR;
            int c = idx >> 5, q = idx & 31;
            float4 v = *(const float4*)(Lf + c * 128 + 4 * q);
            uint32_t h0, l0, h1, l1;
            split_pair(v.x, v.y, h0, l0);
            split_pair(v.z, v.w, h1, l1);
            uint32_t off = (uint32_t)(c * 272 + 8 * q);
            sts64(lh, off, h0, h1);
            sts64(ll, off, l0, l1);
        }
        #pragma unroll
        for (int it = 0; it < 3; it++) {
            int idx = tid + it * NTHR;
            if (idx < CHS * 44) {
                int c = idx / 44, q = idx - c * 44;
                float4 v = *(const float4*)(Rf + c * 176 + 4 * q);
                uint32_t h0, l0, h1, l1;
                split_pair(v.x, v.y, h0, l0);
                split_pair(v.z, v.w, h1, l1);
                uint32_t off = (uint32_t)(c * 368 + 8 * q);
                sts64(rh, off, h0, h1);
                sts64(rl, off, l0, l1);
            }
        }
    };

    // per-lane ldmatrix address offsets (matrix m = lane>>3, row r = lane&7)
    const int mat = lane >> 3, r8 = lane & 7;
    // A tiles [k][i]: mats (i0,k0-7),(i0+8,k0-7),(i0,k8-15),(i0+8,k8-15)
    const uint32_t a_off = (uint32_t)((r8 + 8 * (mat >> 1)) * 272 + (i0 + 8 * (mat & 1)) * 2);
    // B tiles [k][g]: mats (k0-7,g),(k8-15,g),(k0-7,g+8),(k8-15,g+8); g base = i0
    const uint32_t b_off = (uint32_t)((r8 + 8 * (mat & 1)) * 368 + (i0 + 8 * (mat >> 1)) * 2);

    float acc[8][4];
    #pragma unroll
    for (int j = 0; j < 8; j++)
        #pragma unroll
        for (int q = 0; q < 4; q++) acc[j][q] = 0.0f;

    // ---- 24 HMMAs per warp per chunk: 3 split terms x 8 n-frags ----
    auto compute = [&](int buf) {
        uint32_t ah[4], al[4];
        ldsm4t(ah, smb + OFF_LH + buf * LH_B + a_off);
        ldsm4t(al, smb + OFF_LL + buf * LH_B + a_off);
        uint32_t rhb = smb + OFF_RH + buf * RH_B + b_off;
        uint32_t rlb = smb + OFF_RL + buf * RH_B + b_off;
        #pragma unroll
        for (int jb = 0; jb < 4; jb++) {           // 16 g-cols per jb (2 n-frags)
            uint32_t bh[4], bl[4];
            ldsm4t(bh, rhb + jb * 32);
            ldsm4t(bl, rlb + jb * 32);
            mma16816(acc[2 * jb],     ah, bh);
            mma16816(acc[2 * jb],     ah, bl);
            mma16816(acc[2 * jb],     al, bh);
            mma16816(acc[2 * jb + 1], ah, bh + 2);
            mma16816(acc[2 * jb + 1], ah, bl + 2);
            mma16816(acc[2 * jb + 1], al, bh + 2);
        }
    };

    // ============ pipeline: ONE barrier per chunk, tensor/ALU overlapped ============
    // window s: compute(s) | wait own cp(s+1) | convert(s+1) | issue cp(s+2) | sync
    cp_stage(0, 0);
    cp_stage(1, 1);
    asm volatile("cp.async.wait_group 1;");   // own cp(0) done (self-data only)
    convert(0);
    __syncthreads();                          // bf16 buf0 complete across CTA

    for (int s = 0; s < NC; s++) {
        compute(s & 1);
        if (s + 1 < NC) {
            asm volatile("cp.async.wait_group 0;");   // own cp(s+1) landed
            convert((s + 1) & 1);
            if (s + 2 < NC) cp_stage(s + 2, s & 1);   // fp32 buf s&1 free since prev sync
        }
        __syncthreads();
    }

    // ---- epilogue: frags -> smem G[128][65] -> coalesced band stores ----
    float* Gs = (float*)sm;                   // dead fp32 staging region
    {
        int gid = lane >> 2, t4 = lane & 3;
        int ro = (i0 + gid) * GSTR, c0 = 2 * t4;
        #pragma unroll
        for (int j = 0; j < 8; j++) {
            Gs[ro + 8 * j + c0]                 = acc[j][0];
            Gs[ro + 8 * j + c0 + 1]             = acc[j][1];
            Gs[ro + 8 * GSTR + 8 * j + c0]      = acc[j][2];
            Gs[ro + 8 * GSTR + 8 * j + c0 + 1]  = acc[j][3];
        }
    }
    __syncthreads();
    {
        int i  = tid & 127;
        int dh = (tid >> 7) * 24;
        if (w0 + i < WW) {
            #pragma unroll
            for (int dj = 0; dj < 24; dj++) {
                int d = dh + dj;    // g - i0 = (i&15) + 48 - d
                out[(((size_t)(n * DD + d)) * HH + h) * WW + w0 + i] =
                    Gs[i * GSTR + (i & 15) + 48 - d];
            }
        }
    }
}

extern "C" void kernel_launch(void* const* d_in, const int* in_sizes, int n_in,
                              void* d_out, int out_size)
{
    const float* left  = (const float*)d_in[0];
    const float* right = (const float*)d_in[1];
    float* out = (float*)d_out;

    cudaFuncSetAttribute(cost_volume_mma_kernel,
                         cudaFuncAttributeMaxDynamicSharedMemorySize, SMEM_TOTAL);

    dim3 grid((WW + MT - 1) / MT, HH, NB);   // (3, 160, 4)
    cost_volume_mma_kernel<<<grid, NTHR, SMEM_TOTAL>>>(left, right, out);
}

// round 15
// speedup vs baseline: 1.3586x; 1.0828x over previous
#include <cuda_runtime.h>
#include <cuda_fp16.h>
#include <cstdint>

// Problem constants (fixed by setup_inputs)
#define NB 4
#define CC 128
#define HH 160
#define WW 320
#define DD 48
#define CHAN_STRIDE (HH * WW)

#define NTHR 256        // 8 warps, each owns 16 w-rows + its 64-wide g band
#define MT   128        // w rows per CTA tile
#define CHS  16         // channels per pipeline chunk
#define NC   (CC / CHS) // 8 chunks

// ---- smem byte layout (dynamic) ----
#define OFF_FL 0                         // fp32 L stage [2][16][128]
#define FL_B   (CHS * 128 * 4)           // 8192
#define OFF_FR (OFF_FL + 2 * FL_B)       // 16384; fp32 R stage [2][16][176]
#define FR_B   (CHS * 176 * 4)           // 11264
#define OFF_LH (OFF_FR + 2 * FR_B)       // 38912; fp16 Lh [2][16][136] (272B rows)
#define LH_B   (CHS * 136 * 2)           // 4352
#define OFF_LL (OFF_LH + 2 * LH_B)       // 47616; fp16 Ll
#define OFF_RH (OFF_LL + 2 * LH_B)       // 56320; fp16 Rh [2][16][184] (368B rows)
#define RH_B   (CHS * 184 * 2)           // 5888
#define SMEM_TOTAL (OFF_RH + 2 * RH_B)   // 68096
// epilogue G[128][65] fp32 (33280 B) fits in the dead fp32 staging region
#define GSTR 65

__device__ __forceinline__ uint32_t smem_u32(const void* p) {
    return (uint32_t)__cvta_generic_to_shared(p);
}
// 16B async copy, global->shared, zero-fill when bytes==0 (halo padding).
__device__ __forceinline__ void cp16(uint32_t dst, const void* src, int bytes) {
    asm volatile("cp.async.cg.shared.global [%0], [%1], 16, %2;"
                 :: "r"(dst), "l"(src), "r"(bytes));
}
// ldmatrix 4x 8x8 b16 tiles, transposed in HW
__device__ __forceinline__ void ldsm4t(uint32_t* r, uint32_t addr) {
    asm volatile("ldmatrix.sync.aligned.m8n8.x4.trans.shared.b16 {%0,%1,%2,%3}, [%4];"
                 : "=r"(r[0]), "=r"(r[1]), "=r"(r[2]), "=r"(r[3]) : "r"(addr));
}
// D(16x8,f32) += A(16x16,f16 row) * B(16x8,f16 col)
__device__ __forceinline__ void mma16816(float* d, const uint32_t* a, const uint32_t* b) {
    asm volatile(
        "mma.sync.aligned.m16n8k16.row.col.f32.f16.f16.f32 "
        "{%0,%1,%2,%3}, {%4,%5,%6,%7}, {%8,%9}, {%0,%1,%2,%3};"
        : "+f"(d[0]), "+f"(d[1]), "+f"(d[2]), "+f"(d[3])
        : "r"(a[0]), "r"(a[1]), "r"(a[2]), "r"(a[3]), "r"(b[0]), "r"(b[1]));
}
// fp32 pair -> fp16x2 hi word + fp16x2 residual word (lo 16 bits = first element)
__device__ __forceinline__ void split_pair_f16(float a, float b, uint32_t& hi, uint32_t& lo) {
    __half2 h2 = __floats2half2_rn(a, b);
    hi = *reinterpret_cast<uint32_t*>(&h2);
    float ra = a - __half2float(__low2half(h2));
    float rb = b - __half2float(__high2half(h2));
    __half2 l2 = __floats2half2_rn(ra, rb);
    lo = *reinterpret_cast<uint32_t*>(&l2);
}
// fp32 pair -> fp16x2 word (plain rounding, for R)
__device__ __forceinline__ uint32_t cvt_pair_f16(float a, float b) {
    __half2 h2 = __floats2half2_rn(a, b);
    return *reinterpret_cast<uint32_t*>(&h2);
}
// store two 32-bit words as one STS.64
__device__ __forceinline__ void sts64(char* base, uint32_t off, uint32_t a, uint32_t b) {
    asm volatile("st.shared.v2.u32 [%0], {%1, %2};"
                 :: "r"(smem_u32(base) + off), "r"(a), "r"(b) : "memory");
}

__global__ void __launch_bounds__(NTHR, 2)
cost_volume_mma_kernel(const float* __restrict__ left,
                       const float* __restrict__ right,
                       float* __restrict__ out)
{
    extern __shared__ char sm[];
    const uint32_t smb = smem_u32(sm);
    const int tid  = threadIdx.x;
    const int lane = tid & 31;
    const int wid  = tid >> 5;            // 0..7
    const int i0   = wid * 16;            // warp's w-rows i0..i0+15; g-band [i0, i0+64)
    const int w0   = blockIdx.x * MT;     // 0,128,256 (last tile zero-padded)
    const int h    = blockIdx.y;
    const int n    = blockIdx.z;

    const float* lrow = left  + (size_t)n * CC * CHAN_STRIDE + (size_t)h * WW;
    const float* rrow = right + (size_t)n * CC * CHAN_STRIDE + (size_t)h * WW;

    // ---- cp.async stage of one 16-channel chunk (fp32) ----
    // thread->data mapping MUST match convert() below (self-owned data).
    auto cp_stage = [&](int s, int buf) {
        const float* lb = lrow + (size_t)(s * CHS) * CHAN_STRIDE;
        const float* rb = rrow + (size_t)(s * CHS) * CHAN_STRIDE;
        #pragma unroll
        for (int it = 0; it < 2; it++) {           // L: 512 float4
            int idx = tid + it * NTHR;
            int c = idx >> 5, q = idx & 31;
            int gw = w0 + 4 * q;
            bool ok = (gw < WW);
            cp16(smb + OFF_FL + buf * FL_B + c * 512 + 16 * q,
                 ok ? lb + (size_t)c * CHAN_STRIDE + gw : lb, ok ? 16 : 0);
        }
        #pragma unroll
        for (int it = 0; it < 3; it++) {           // R: 704 float4
            int idx = tid + it * NTHR;
            if (idx < CHS * 44) {
                int c = idx / 44, q = idx - c * 44;
                int gw = w0 - 48 + 4 * q;
                bool ok = (gw >= 0) && (gw < WW);
                cp16(smb + OFF_FR + buf * FR_B + c * 704 + 16 * q,
                     ok ? rb + (size_t)c * CHAN_STRIDE + gw : rb, ok ? 16 : 0);
            }
        }
        asm volatile("cp.async.commit_group;");
    };

    // ---- convert: each thread converts exactly the float4s it cp'd ----
    // L -> split (Lh, Ll); R -> plain fp16 (Rh). Thread-local wait suffices.
    auto convert = [&](int buf) {
        const float* Lf = (const float*)(sm + OFF_FL + buf * FL_B);
        const float* Rf = (const float*)(sm + OFF_FR + buf * FR_B);
        char* lh = sm + OFF_LH + buf * LH_B;
        char* ll = sm + OFF_LL + buf * LH_B;
        char* rh = sm + OFF_RH + buf * RH_B;
        #pragma unroll
        for (int it = 0; it < 2; it++) {
            int idx = tid + it * NTHR;
            int c = idx >> 5, q = idx & 31;
            float4 v = *(const float4*)(Lf + c * 128 + 4 * q);
            uint32_t h0, l0, h1, l1;
            split_pair_f16(v.x, v.y, h0, l0);
            split_pair_f16(v.z, v.w, h1, l1);
            uint32_t off = (uint32_t)(c * 272 + 8 * q);
            sts64(lh, off, h0, h1);
            sts64(ll, off, l0, l1);
        }
        #pragma unroll
        for (int it = 0; it < 3; it++) {
            int idx = tid + it * NTHR;
            if (idx < CHS * 44) {
                int c = idx / 44, q = idx - c * 44;
                float4 v = *(const float4*)(Rf + c * 176 + 4 * q);
                uint32_t h0 = cvt_pair_f16(v.x, v.y);
                uint32_t h1 = cvt_pair_f16(v.z, v.w);
                sts64(rh, (uint32_t)(c * 368 + 8 * q), h0, h1);
            }
        }
    };

    // per-lane ldmatrix address offsets (matrix m = lane>>3, row r = lane&7)
    const int mat = lane >> 3, r8 = lane & 7;
    // A tiles [k][i]: mats (i0,k0-7),(i0+8,k0-7),(i0,k8-15),(i0+8,k8-15)
    const uint32_t a_off = (uint32_t)((r8 + 8 * (mat >> 1)) * 272 + (i0 + 8 * (mat & 1)) * 2);
    // B tiles [k][g]: mats (k0-7,g),(k8-15,g),(k0-7,g+8),(k8-15,g+8); g base = i0
    const uint32_t b_off = (uint32_t)((r8 + 8 * (mat & 1)) * 368 + (i0 + 8 * (mat >> 1)) * 2);

    float acc[8][4];
    #pragma unroll
    for (int j = 0; j < 8; j++)
        #pragma unroll
        for (int q = 0; q < 4; q++) acc[j][q] = 0.0f;

    // ---- 16 HMMAs per warp per chunk: (Lh + Ll)·Rh = L·Rh over 8 n-frags ----
    auto compute = [&](int buf) {
        uint32_t ah[4], al[4];
        ldsm4t(ah, smb + OFF_LH + buf * LH_B + a_off);
        ldsm4t(al, smb + OFF_LL + buf * LH_B + a_off);
        uint32_t rhb = smb + OFF_RH + buf * RH_B + b_off;
        #pragma unroll
        for (int jb = 0; jb < 4; jb++) {           // 16 g-cols per jb (2 n-frags)
            uint32_t bh[4];
            ldsm4t(bh, rhb + jb * 32);
            mma16816(acc[2 * jb],     ah, bh);
            mma16816(acc[2 * jb],     al, bh);
            mma16816(acc[2 * jb + 1], ah, bh + 2);
            mma16816(acc[2 * jb + 1], al, bh + 2);
        }
    };

    // ============ pipeline: ONE barrier per chunk, tensor/ALU overlapped ============
    // window s: compute(s) | wait own cp(s+1) | convert(s+1) | issue cp(s+2) | sync
    cp_stage(0, 0);
    cp_stage(1, 1);
    asm volatile("cp.async.wait_group 1;");   // own cp(0) done (self-data only)
    convert(0);
    __syncthreads();                          // fp16 buf0 complete across CTA

    for (int s = 0; s < NC; s++) {
        compute(s & 1);
        if (s + 1 < NC) {
            asm volatile("cp.async.wait_group 0;");   // own cp(s+1) landed
            convert((s + 1) & 1);
            if (s + 2 < NC) cp_stage(s + 2, s & 1);   // fp32 buf s&1 free since prev sync
        }
        __syncthreads();
    }

    // ---- epilogue: frags -> smem G[128][65] -> coalesced band stores ----
    float* Gs = (float*)sm;                   // dead fp32 staging region
    {
        int gid = lane >> 2, t4 = lane & 3;
        int ro = (i0 + gid) * GSTR, c0 = 2 * t4;
        #pragma unroll
        for (int j = 0; j < 8; j++) {
            Gs[ro + 8 * j + c0]                 = acc[j][0];
            Gs[ro + 8 * j + c0 + 1]             = acc[j][1];
            Gs[ro + 8 * GSTR + 8 * j + c0]      = acc[j][2];
            Gs[ro + 8 * GSTR + 8 * j + c0 + 1]  = acc[j][3];
        }
    }
    __syncthreads();
    {
        int i  = tid & 127;
        int dh = (tid >> 7) * 24;
        if (w0 + i < WW) {
            #pragma unroll
            for (int dj = 0; dj < 24; dj++) {
                int d = dh + dj;    // g - i0 = (i&15) + 48 - d
                out[(((size_t)(n * DD + d)) * HH + h) * WW + w0 + i] =
                    Gs[i * GSTR + (i & 15) + 48 - d];
            }
        }
    }
}

extern "C" void kernel_launch(void* const* d_in, const int* in_sizes, int n_in,
                              void* d_out, int out_size)
{
    const float* left  = (const float*)d_in[0];
    const float* right = (const float*)d_in[1];
    float* out = (float*)d_out;

    cudaFuncSetAttribute(cost_volume_mma_kernel,
                         cudaFuncAttributeMaxDynamicSharedMemorySize, SMEM_TOTAL);

    dim3 grid((WW + MT - 1) / MT, HH, NB);   // (3, 160, 4)
    cost_volume_mma_kernel<<<grid, NTHR, SMEM_TOTAL>>>(left, right, out);
}

// round 17
// speedup vs baseline: 1.5815x; 1.1641x over previous
#include <cuda_runtime.h>
#include <cuda_fp16.h>
#include <cstdint>

// Problem constants (fixed by setup_inputs)
#define NB 4
#define CC 128
#define HH 160
#define WW 320
#define DD 48
#define CHAN_STRIDE (HH * WW)

#define NTHR 256        // 8 warps, each owns 16 w-rows + its 64-wide g band
#define MT   128        // w rows per CTA tile
#define CHS  16         // channels per pipeline chunk
#define NC   (CC / CHS) // 8 chunks

// ---- smem byte layout (dynamic) ----
// fp32 staging: TRIPLE buffered (2 cp.async groups in flight)
#define FL_B   (CHS * 128 * 4)           // 8192
#define FR_B   (CHS * 176 * 4)           // 11264
#define OFF_FL 0                         // 3 x FL_B = 24576
#define OFF_FR (OFF_FL + 3 * FL_B)       // 24576; 3 x FR_B = 33792
#define OFF_LH (OFF_FR + 3 * FR_B)       // 58368; fp16 Lh [2][16][136] (272B rows)
#define LH_B   (CHS * 136 * 2)           // 4352
#define OFF_LL (OFF_LH + 2 * LH_B)       // 67072; fp16 Ll
#define OFF_RH (OFF_LL + 2 * LH_B)       // 75776; fp16 Rh [2][16][184] (368B rows)
#define RH_B   (CHS * 184 * 2)           // 5888
#define SMEM_TOTAL (OFF_RH + 2 * RH_B)   // 87552
// epilogue G[128][65] fp32 (33280 B) fits in the dead fp32 staging region
#define GSTR 65

__device__ __forceinline__ uint32_t smem_u32(const void* p) {
    return (uint32_t)__cvta_generic_to_shared(p);
}
// 16B async copy, global->shared, zero-fill when bytes==0 (halo padding).
__device__ __forceinline__ void cp16(uint32_t dst, const void* src, int bytes) {
    asm volatile("cp.async.cg.shared.global [%0], [%1], 16, %2;"
                 :: "r"(dst), "l"(src), "r"(bytes));
}
// ldmatrix 4x 8x8 b16 tiles, transposed in HW
__device__ __forceinline__ void ldsm4t(uint32_t* r, uint32_t addr) {
    asm volatile("ldmatrix.sync.aligned.m8n8.x4.trans.shared.b16 {%0,%1,%2,%3}, [%4];"
                 : "=r"(r[0]), "=r"(r[1]), "=r"(r[2]), "=r"(r[3]) : "r"(addr));
}
// D(16x8,f32) += A(16x16,f16 row) * B(16x8,f16 col)
__device__ __forceinline__ void mma16816(float* d, const uint32_t* a, const uint32_t* b) {
    asm volatile(
        "mma.sync.aligned.m16n8k16.row.col.f32.f16.f16.f32 "
        "{%0,%1,%2,%3}, {%4,%5,%6,%7}, {%8,%9}, {%0,%1,%2,%3};"
        : "+f"(d[0]), "+f"(d[1]), "+f"(d[2]), "+f"(d[3])
        : "r"(a[0]), "r"(a[1]), "r"(a[2]), "r"(a[3]), "r"(b[0]), "r"(b[1]));
}
// fp32 pair -> fp16x2 hi word + fp16x2 residual word (lo 16 bits = first element)
__device__ __forceinline__ void split_pair_f16(float a, float b, uint32_t& hi, uint32_t& lo) {
    __half2 h2 = __floats2half2_rn(a, b);
    hi = *reinterpret_cast<uint32_t*>(&h2);
    float ra = a - __half2float(__low2half(h2));
    float rb = b - __half2float(__high2half(h2));
    __half2 l2 = __floats2half2_rn(ra, rb);
    lo = *reinterpret_cast<uint32_t*>(&l2);
}
// fp32 pair -> fp16x2 word (plain rounding, for R)
__device__ __forceinline__ uint32_t cvt_pair_f16(float a, float b) {
    __half2 h2 = __floats2half2_rn(a, b);
    return *reinterpret_cast<uint32_t*>(&h2);
}
// store two 32-bit words as one STS.64
__device__ __forceinline__ void sts64(char* base, uint32_t off, uint32_t a, uint32_t b) {
    asm volatile("st.shared.v2.u32 [%0], {%1, %2};"
                 :: "r"(smem_u32(base) + off), "r"(a), "r"(b) : "memory");
}

__global__ void __launch_bounds__(NTHR, 2)
cost_volume_mma_kernel(const float* __restrict__ left,
                       const float* __restrict__ right,
                       float* __restrict__ out)
{
    extern __shared__ char sm[];
    const uint32_t smb = smem_u32(sm);
    const int tid  = threadIdx.x;
    const int lane = tid & 31;
    const int wid  = tid >> 5;            // 0..7
    const int i0   = wid * 16;            // warp's w-rows i0..i0+15; g-band [i0, i0+64)
    const int w0   = blockIdx.x * MT;     // 0,128,256 (last tile zero-padded)
    const int h    = blockIdx.y;
    const int n    = blockIdx.z;

    const float* lrow = left  + (size_t)n * CC * CHAN_STRIDE + (size_t)h * WW;
    const float* rrow = right + (size_t)n * CC * CHAN_STRIDE + (size_t)h * WW;

    // ---- cp.async stage of chunk s into fp32 buffer b3 (0..2) ----
    // thread->data mapping MUST match convert() below (self-owned data).
    auto cp_stage = [&](int s, int b3) {
        const float* lb = lrow + (size_t)(s * CHS) * CHAN_STRIDE;
        const float* rb = rrow + (size_t)(s * CHS) * CHAN_STRIDE;
        #pragma unroll
        for (int it = 0; it < 2; it++) {           // L: 512 float4
            int idx = tid + it * NTHR;
            int c = idx >> 5, q = idx & 31;
            int gw = w0 + 4 * q;
            bool ok = (gw < WW);
            cp16(smb + OFF_FL + b3 * FL_B + c * 512 + 16 * q,
                 ok ? lb + (size_t)c * CHAN_STRIDE + gw : lb, ok ? 16 : 0);
        }
        #pragma unroll
        for (int it = 0; it < 3; it++) {           // R: 704 float4
            int idx = tid + it * NTHR;
            if (idx < CHS * 44) {
                int c = idx / 44, q = idx - c * 44;
                int gw = w0 - 48 + 4 * q;
                bool ok = (gw >= 0) && (gw < WW);
                cp16(smb + OFF_FR + b3 * FR_B + c * 704 + 16 * q,
                     ok ? rb + (size_t)c * CHAN_STRIDE + gw : rb, ok ? 16 : 0);
            }
        }
        asm volatile("cp.async.commit_group;");
    };

    // ---- convert fp32 buf b3 -> fp16 tiles buf b2; self-owned data only ----
    auto convert = [&](int b3, int b2) {
        const float* Lf = (const float*)(sm + OFF_FL + b3 * FL_B);
        const float* Rf = (const float*)(sm + OFF_FR + b3 * FR_B);
        char* lh = sm + OFF_LH + b2 * LH_B;
        char* ll = sm + OFF_LL + b2 * LH_B;
        char* rh = sm + OFF_RH + b2 * RH_B;
        #pragma unroll
        for (int it = 0; it < 2; it++) {
            int idx = tid + it * NTHR;
            int c = idx >> 5, q = idx & 31;
            float4 v = *(const float4*)(Lf + c * 128 + 4 * q);
            uint32_t h0, l0, h1, l1;
            split_pair_f16(v.x, v.y, h0, l0);
            split_pair_f16(v.z, v.w, h1, l1);
            uint32_t off = (uint32_t)(c * 272 + 8 * q);
            sts64(lh, off, h0, h1);
            sts64(ll, off, l0, l1);
        }
        #pragma unroll
        for (int it = 0; it < 3; it++) {
            int idx = tid + it * NTHR;
            if (idx < CHS * 44) {
                int c = idx / 44, q = idx - c * 44;
                float4 v = *(const float4*)(Rf + c * 176 + 4 * q);
                uint32_t h0 = cvt_pair_f16(v.x, v.y);
                uint32_t h1 = cvt_pair_f16(v.z, v.w);
                sts64(rh, (uint32_t)(c * 368 + 8 * q), h0, h1);
            }
        }
    };

    // per-lane ldmatrix address offsets (matrix m = lane>>3, row r = lane&7)
    const int mat = lane >> 3, r8 = lane & 7;
    // A tiles [k][i]: mats (i0,k0-7),(i0+8,k0-7),(i0,k8-15),(i0+8,k8-15)
    const uint32_t a_off = (uint32_t)((r8 + 8 * (mat >> 1)) * 272 + (i0 + 8 * (mat & 1)) * 2);
    // B tiles [k][g]: mats (k0-7,g),(k8-15,g),(k0-7,g+8),(k8-15,g+8); g base = i0
    const uint32_t b_off = (uint32_t)((r8 + 8 * (mat & 1)) * 368 + (i0 + 8 * (mat >> 1)) * 2);

    float acc[8][4];
    #pragma unroll
    for (int j = 0; j < 8; j++)
        #pragma unroll
        for (int q = 0; q < 4; q++) acc[j][q] = 0.0f;

    // ---- 16 HMMAs per warp per chunk: (Lh + Ll)·Rh = L·Rh over 8 n-frags ----
    auto compute = [&](int b2) {
        uint32_t ah[4], al[4];
        ldsm4t(ah, smb + OFF_LH + b2 * LH_B + a_off);
        ldsm4t(al, smb + OFF_LL + b2 * LH_B + a_off);
        uint32_t rhb = smb + OFF_RH + b2 * RH_B + b_off;
        #pragma unroll
        for (int jb = 0; jb < 4; jb++) {           // 16 g-cols per jb (2 n-frags)
            uint32_t bh[4];
            ldsm4t(bh, rhb + jb * 32);
            mma16816(acc[2 * jb],     ah, bh);
            mma16816(acc[2 * jb],     al, bh);
            mma16816(acc[2 * jb + 1], ah, bh + 2);
            mma16816(acc[2 * jb + 1], al, bh + 2);
        }
    };

    // ====== pipeline: 2 cp groups in flight, prefetch distance = 2 windows ======
    // Ledger at window s (steady state): pending = {cp(s+1), cp(s+2)} before the
    // wait; wait_group 1 => cp(s+1) landed. TAIL: once s+2 >= NC no new groups
    // are issued, pending = {cp(s+1)} only -> wait_group 1 would NOT guarantee
    // cp(s+1)!  Use wait_group 0 there (this was the R16 data race).
    cp_stage(0, 0);
    cp_stage(1, 1);
    cp_stage(2, 2);
    asm volatile("cp.async.wait_group 2;");   // cp(0) done, cp(1)/cp(2) in flight
    convert(0, 0);
    __syncthreads();                          // fp16 buf0 complete across CTA

    for (int s = 0; s < NC; s++) {
        compute(s & 1);
        if (s + 1 < NC) {
            if (s + 2 < NC) { asm volatile("cp.async.wait_group 1;"); }
            else            { asm volatile("cp.async.wait_group 0;"); }
            convert((s + 1) % 3, (s + 1) & 1);
            if (s + 3 < NC) cp_stage(s + 3, s % 3);   // buf s%3 consumed last window
        }
        __syncthreads();
    }

    // ---- epilogue: frags -> smem G[128][65] -> coalesced band stores ----
    float* Gs = (float*)sm;                   // dead fp32 staging region
    {
        int gid = lane >> 2, t4 = lane & 3;
        int ro = (i0 + gid) * GSTR, c0 = 2 * t4;
        #pragma unroll
        for (int j = 0; j < 8; j++) {
            Gs[ro + 8 * j + c0]                 = acc[j][0];
            Gs[ro + 8 * j + c0 + 1]             = acc[j][1];
            Gs[ro + 8 * GSTR + 8 * j + c0]      = acc[j][2];
            Gs[ro + 8 * GSTR + 8 * j + c0 + 1]  = acc[j][3];
        }
    }
    __syncthreads();
    {
        int i  = tid & 127;
        int dh = (tid >> 7) * 24;
        if (w0 + i < WW) {
            #pragma unroll
            for (int dj = 0; dj < 24; dj++) {
                int d = dh + dj;    // g - i0 = (i&15) + 48 - d
                out[(((size_t)(n * DD + d)) * HH + h) * WW + w0 + i] =
                    Gs[i * GSTR + (i & 15) + 48 - d];
            }
        }
    }
}

extern "C" void kernel_launch(void* const* d_in, const int* in_sizes, int n_in,
                              void* d_out, int out_size)
{
    const float* left  = (const float*)d_in[0];
    const float* right = (const float*)d_in[1];
    float* out = (float*)d_out;

    cudaFuncSetAttribute(cost_volume_mma_kernel,
                         cudaFuncAttributeMaxDynamicSharedMemorySize, SMEM_TOTAL);

    dim3 grid((WW + MT - 1) / MT, HH, NB);   // (3, 160, 4)
    cost_volume_mma_kernel<<<grid, NTHR, SMEM_TOTAL>>>(left, right, out);
}